// round 6
// baseline (speedup 1.0000x reference)
#include <cuda_runtime.h>

// Math collapse: softmax over a size-1 axis == 1.0 exactly, so
//   out[b,c,f] = sum_t x[b,t,f]   (context/W/b are dead inputs).
// One DRAM-bound kernel: reduce over T, broadcast over C.

#define B_ 32
#define T_ 512
#define C_ 256
#define F_ 512

static constexpr int F4      = F_ / 4;        // 128 float4 per row
static constexpr int TILE_F4 = 16;            // 64 floats per f-tile
static constexpr int NTILES  = F4 / TILE_F4;  // 8 tiles
static constexpr int TG      = 16;            // t-groups per block
static constexpr int TPB     = TILE_F4 * TG;  // 256 threads
static constexpr int T_PER   = T_ / TG;       // 32 timesteps per thread

__global__ __launch_bounds__(TPB)
void attn_collapse_kernel(const float* __restrict__ x, float* __restrict__ out) {
    const int blk  = blockIdx.x;        // 0 .. B_*NTILES-1
    const int b    = blk / NTILES;
    const int tile = blk % NTILES;
    const int f4l  = threadIdx.x % TILE_F4;   // lane within f-tile
    const int tg   = threadIdx.x / TILE_F4;   // t-group 0..15
    const int f4   = tile * TILE_F4 + f4l;

    const float4* xb = reinterpret_cast<const float4*>(x)
                     + (size_t)b * T_ * F4 + f4;

    // Partial sum over this thread's 32 timesteps (independent loads -> MLP=32)
    float4 acc = make_float4(0.f, 0.f, 0.f, 0.f);
    const int t0 = tg * T_PER;
#pragma unroll
    for (int i = 0; i < T_PER; ++i) {
        float4 v = __ldg(&xb[(size_t)(t0 + i) * F4]);
        acc.x += v.x; acc.y += v.y; acc.z += v.z; acc.w += v.w;
    }

    // Tree-reduce across the 16 t-groups in shared memory
    __shared__ float4 s[TG][TILE_F4];
    s[tg][f4l] = acc;
    __syncthreads();
#pragma unroll
    for (int stride = TG / 2; stride > 0; stride >>= 1) {
        if (tg < stride) {
            float4 o = s[tg + stride][f4l];
            float4 m = s[tg][f4l];
            m.x += o.x; m.y += o.y; m.z += o.z; m.w += o.w;
            s[tg][f4l] = m;
        }
        __syncthreads();
    }
    const float4 sum = s[0][f4l];   // column sum for this (b, f4)

    // Broadcast across C: thread (tg, f4l) writes c = tg, tg+16, ..., tg+240.
    // Within a half-warp f4l varies fastest -> 256B contiguous stores.
    float4* ob = reinterpret_cast<float4*>(out) + (size_t)b * C_ * F4 + f4;
#pragma unroll
    for (int k = 0; k < C_ / TG; ++k) {
        const int c = k * TG + tg;
        ob[(size_t)c * F4] = sum;
    }
}

extern "C" void kernel_launch(void* const* d_in, const int* in_sizes, int n_in,
                              void* d_out, int out_size) {
    (void)in_sizes; (void)n_in; (void)out_size;
    const float* x = (const float*)d_in[0];   // [B,T,F]; context/W/b unused (dead math)
    float* out = (float*)d_out;               // [B,C,F]
    attn_collapse_kernel<<<B_ * NTILES, TPB>>>(x, out);
}

// round 7
// speedup vs baseline: 1.2620x; 1.2620x over previous
#include <cuda_runtime.h>

// Math collapse: softmax over a size-1 axis == 1.0 exactly, so
//   out[b,c,f] = sum_t x[b,t,f]   (context/W/b are dead inputs).
// One DRAM-bound kernel: reduce over T, broadcast over C.

#define B_ 32
#define T_ 512
#define C_ 256
#define F_ 512

static constexpr int F4      = F_ / 4;        // 128 float4 per row
static constexpr int TILE_F4 = 16;            // 64 floats per f-tile
static constexpr int NTILES  = F4 / TILE_F4;  // 8 tiles
static constexpr int TG      = 16;            // t-groups per block
static constexpr int TPB     = TILE_F4 * TG;  // 256 threads
static constexpr int T_PER   = T_ / TG;       // 32 timesteps per thread

__global__ __launch_bounds__(TPB)
void attn_collapse_kernel(const float* __restrict__ x, float* __restrict__ out) {
    const int blk  = blockIdx.x;        // 0 .. B_*NTILES-1
    const int b    = blk / NTILES;
    const int tile = blk % NTILES;
    const int f4l  = threadIdx.x % TILE_F4;   // lane within f-tile
    const int tg   = threadIdx.x / TILE_F4;   // t-group 0..15
    const int f4   = tile * TILE_F4 + f4l;

    const float4* xb = reinterpret_cast<const float4*>(x)
                     + (size_t)b * T_ * F4 + f4;

    // Partial sum over this thread's 32 timesteps (independent loads -> MLP=32)
    float4 acc = make_float4(0.f, 0.f, 0.f, 0.f);
    const int t0 = tg * T_PER;
#pragma unroll
    for (int i = 0; i < T_PER; ++i) {
        float4 v = __ldg(&xb[(size_t)(t0 + i) * F4]);
        acc.x += v.x; acc.y += v.y; acc.z += v.z; acc.w += v.w;
    }

    // Tree-reduce across the 16 t-groups in shared memory
    __shared__ float4 s[TG][TILE_F4];
    s[tg][f4l] = acc;
    __syncthreads();
#pragma unroll
    for (int stride = TG / 2; stride > 0; stride >>= 1) {
        if (tg < stride) {
            float4 o = s[tg + stride][f4l];
            float4 m = s[tg][f4l];
            m.x += o.x; m.y += o.y; m.z += o.z; m.w += o.w;
            s[tg][f4l] = m;
        }
        __syncthreads();
    }
    const float4 sum = s[0][f4l];   // column sum for this (b, f4)

    // Broadcast across C: thread (tg, f4l) writes c = tg, tg+16, ..., tg+240.
    // Within a half-warp f4l varies fastest -> 256B contiguous stores.
    float4* ob = reinterpret_cast<float4*>(out) + (size_t)b * C_ * F4 + f4;
#pragma unroll
    for (int k = 0; k < C_ / TG; ++k) {
        const int c = k * TG + tg;
        ob[(size_t)c * F4] = sum;
    }
}

extern "C" void kernel_launch(void* const* d_in, const int* in_sizes, int n_in,
                              void* d_out, int out_size) {
    (void)in_sizes; (void)n_in; (void)out_size;
    const float* x = (const float*)d_in[0];   // [B,T,F]; context/W/b unused (dead math)
    float* out = (float*)d_out;               // [B,C,F]
    attn_collapse_kernel<<<B_ * NTILES, TPB>>>(x, out);
}